// round 5
// baseline (speedup 1.0000x reference)
#include <cuda_runtime.h>
#include <cstdint>
#include <math_constants.h>

// Flash-attention, TF32 mma.sync, fp32 accumulate.
// B=2, H=16, S=2048, DK=DV=64.
// Reference output is a RAW reshape of [B,H,S,DV] -> [B,S,H*DV], i.e. the
// output buffer's memory layout is contiguous [B,H,S,DV]. Store accordingly.
// d_in[0]=key [B,H,S,64], d_in[1]=query, d_in[2]=value (fp32).

namespace {

constexpr int S_LEN    = 2048;
constexpr int DH       = 64;
constexpr int HEADS    = 16;
constexpr int BM       = 128;   // query rows per CTA
constexpr int BN       = 64;    // key rows per tile
constexpr int NTHREADS = 256;   // 8 warps, 16 query rows each

// smem strides (words). Chosen for conflict-free operand LDS:
//  Q/K/P stride 68: bank = 4g + j  -> all 32 distinct
//  V stride 72:     bank = 8j + g  -> all 32 distinct
constexpr int QSTR = 68;
constexpr int KSTR = 68;
constexpr int VSTR = 72;
constexpr int PSTR = 68;

constexpr int SMEM_WORDS = BM * QSTR + BN * KSTR + BN * VSTR + BM * PSTR;
constexpr int SMEM_BYTES = SMEM_WORDS * 4;   // 105,472 B -> 2 CTAs/SM

__device__ __forceinline__ uint32_t f2tf(float x) {
    uint32_t r;
    asm("cvt.rna.tf32.f32 %0, %1;" : "=r"(r) : "f"(x));
    return r;
}

__device__ __forceinline__ float fast_exp2(float x) {
    float y;
    asm("ex2.approx.ftz.f32 %0, %1;" : "=f"(y) : "f"(x));
    return y;
}

__device__ __forceinline__ void mma_tf32(float c[4],
                                         uint32_t a0, uint32_t a1,
                                         uint32_t a2, uint32_t a3,
                                         uint32_t b0, uint32_t b1) {
    asm volatile(
        "mma.sync.aligned.m16n8k8.row.col.f32.tf32.tf32.f32 "
        "{%0,%1,%2,%3}, {%4,%5,%6,%7}, {%8,%9}, {%0,%1,%2,%3};"
        : "+f"(c[0]), "+f"(c[1]), "+f"(c[2]), "+f"(c[3])
        : "r"(a0), "r"(a1), "r"(a2), "r"(a3), "r"(b0), "r"(b1));
}

}  // namespace

__global__ __launch_bounds__(NTHREADS, 2)
void mha_fa_tf32(const float* __restrict__ Kg,
                 const float* __restrict__ Qg,
                 const float* __restrict__ Vg,
                 float* __restrict__ Out) {
    extern __shared__ uint32_t smem[];
    uint32_t* sQ = smem;
    uint32_t* sK = sQ + BM * QSTR;
    uint32_t* sV = sK + BN * KSTR;
    uint32_t* sP = sV + BN * VSTR;

    const int tid  = threadIdx.x;
    const int warp = tid >> 5;
    const int lane = tid & 31;
    const int g    = lane >> 2;   // group id 0..7
    const int j    = lane & 3;    // quad id  0..3
    const int mrow = warp * 16;   // this warp's 16 query rows within the tile

    const int bh = blockIdx.y;    // b*16 + h
    const int qt = blockIdx.x;    // query tile

    const size_t head_base = (size_t)bh * S_LEN * DH;
    const float* Qp = Qg + head_base + (size_t)qt * BM * DH;
    const float* Kp = Kg + head_base;
    const float* Vp = Vg + head_base;

    // ---- load Q tile (pre-scaled by 1/sqrt(dk) = 0.125), convert to tf32 ----
    for (int i = tid * 4; i < BM * DH; i += NTHREADS * 4) {
        float4 v = *reinterpret_cast<const float4*>(Qp + i);
        uint32_t* p = sQ + (i >> 6) * QSTR + (i & 63);
        p[0] = f2tf(v.x * 0.125f);
        p[1] = f2tf(v.y * 0.125f);
        p[2] = f2tf(v.z * 0.125f);
        p[3] = f2tf(v.w * 0.125f);
    }

    float o[8][4];
    #pragma unroll
    for (int n = 0; n < 8; ++n)
        #pragma unroll
        for (int t = 0; t < 4; ++t) o[n][t] = 0.f;

    float m0 = -CUDART_INF_F, m1 = -CUDART_INF_F;  // row maxes (row g, row g+8)
    float l0 = 0.f, l1 = 0.f;                      // row sums
    const float L2E = 1.4426950408889634f;

    for (int kt = 0; kt < S_LEN / BN; ++kt) {
        __syncthreads();  // all warps done with previous sK/sV (and Q visible on iter 0)

        // ---- load K/V tile, convert to tf32 ----
        const float* Kt = Kp + kt * BN * DH;
        const float* Vt = Vp + kt * BN * DH;
        for (int i = tid * 4; i < BN * DH; i += NTHREADS * 4) {
            const int r = i >> 6, c = i & 63;
            float4 kv = *reinterpret_cast<const float4*>(Kt + i);
            uint32_t* pk = sK + r * KSTR + c;
            pk[0] = f2tf(kv.x); pk[1] = f2tf(kv.y);
            pk[2] = f2tf(kv.z); pk[3] = f2tf(kv.w);
            float4 vv = *reinterpret_cast<const float4*>(Vt + i);
            uint32_t* pv = sV + r * VSTR + c;
            pv[0] = f2tf(vv.x); pv[1] = f2tf(vv.y);
            pv[2] = f2tf(vv.z); pv[3] = f2tf(vv.w);
        }
        __syncthreads();

        // ---- S = (Q*scale) @ K^T : 16x64 per warp ----
        float c[8][4];
        #pragma unroll
        for (int n = 0; n < 8; ++n)
            #pragma unroll
            for (int t = 0; t < 4; ++t) c[n][t] = 0.f;

        #pragma unroll
        for (int k0 = 0; k0 < DH; k0 += 8) {
            const uint32_t a0 = sQ[(mrow + g    ) * QSTR + k0 + j];
            const uint32_t a1 = sQ[(mrow + g + 8) * QSTR + k0 + j];
            const uint32_t a2 = sQ[(mrow + g    ) * QSTR + k0 + j + 4];
            const uint32_t a3 = sQ[(mrow + g + 8) * QSTR + k0 + j + 4];
            #pragma unroll
            for (int n = 0; n < 8; ++n) {
                const uint32_t b0 = sK[(n * 8 + g) * KSTR + k0 + j];
                const uint32_t b1 = sK[(n * 8 + g) * KSTR + k0 + j + 4];
                mma_tf32(c[n], a0, a1, a2, a3, b0, b1);
            }
        }

        // ---- online softmax (rows g and g+8; each row owned by one quad) ----
        float mx0 = m0, mx1 = m1;
        #pragma unroll
        for (int n = 0; n < 8; ++n) {
            mx0 = fmaxf(mx0, fmaxf(c[n][0], c[n][1]));
            mx1 = fmaxf(mx1, fmaxf(c[n][2], c[n][3]));
        }
        mx0 = fmaxf(mx0, __shfl_xor_sync(0xffffffffu, mx0, 1));
        mx0 = fmaxf(mx0, __shfl_xor_sync(0xffffffffu, mx0, 2));
        mx1 = fmaxf(mx1, __shfl_xor_sync(0xffffffffu, mx1, 1));
        mx1 = fmaxf(mx1, __shfl_xor_sync(0xffffffffu, mx1, 2));

        const float sc0 = fast_exp2((m0 - mx0) * L2E);  // 0 on first tile (m=-inf)
        const float sc1 = fast_exp2((m1 - mx1) * L2E);
        m0 = mx0; m1 = mx1;

        float s0 = 0.f, s1 = 0.f;
        #pragma unroll
        for (int n = 0; n < 8; ++n) {
            const float p0 = fast_exp2((c[n][0] - m0) * L2E);
            const float p1 = fast_exp2((c[n][1] - m0) * L2E);
            const float p2 = fast_exp2((c[n][2] - m1) * L2E);
            const float p3 = fast_exp2((c[n][3] - m1) * L2E);
            s0 += p0 + p1;
            s1 += p2 + p3;
            // P into warp-private smem rows (layout for A-fragment reload)
            sP[(mrow + g    ) * PSTR + n * 8 + 2 * j    ] = f2tf(p0);
            sP[(mrow + g    ) * PSTR + n * 8 + 2 * j + 1] = f2tf(p1);
            sP[(mrow + g + 8) * PSTR + n * 8 + 2 * j    ] = f2tf(p2);
            sP[(mrow + g + 8) * PSTR + n * 8 + 2 * j + 1] = f2tf(p3);
        }
        s0 += __shfl_xor_sync(0xffffffffu, s0, 1);
        s0 += __shfl_xor_sync(0xffffffffu, s0, 2);
        s1 += __shfl_xor_sync(0xffffffffu, s1, 1);
        s1 += __shfl_xor_sync(0xffffffffu, s1, 2);
        l0 = l0 * sc0 + s0;
        l1 = l1 * sc1 + s1;

        #pragma unroll
        for (int n = 0; n < 8; ++n) {
            o[n][0] *= sc0; o[n][1] *= sc0;
            o[n][2] *= sc1; o[n][3] *= sc1;
        }

        __syncwarp();  // sP rows are warp-private: warp-level sync suffices

        // ---- O += P @ V : 16x64 per warp ----
        #pragma unroll
        for (int k0 = 0; k0 < BN; k0 += 8) {
            const uint32_t a0 = sP[(mrow + g    ) * PSTR + k0 + j];
            const uint32_t a1 = sP[(mrow + g + 8) * PSTR + k0 + j];
            const uint32_t a2 = sP[(mrow + g    ) * PSTR + k0 + j + 4];
            const uint32_t a3 = sP[(mrow + g + 8) * PSTR + k0 + j + 4];
            #pragma unroll
            for (int n = 0; n < 8; ++n) {
                const uint32_t b0 = sV[(k0 + j    ) * VSTR + n * 8 + g];
                const uint32_t b1 = sV[(k0 + j + 4) * VSTR + n * 8 + g];
                mma_tf32(o[n], a0, a1, a2, a3, b0, b1);
            }
        }
    }

    // ---- epilogue: normalize and store ----
    // Raw reshape [B,H,S,DV]->[B,S,H*DV] preserves memory order, so the output
    // buffer layout IS contiguous [B,H,S,DV]: same head_base/row math as inputs.
    const float inv0 = 1.0f / l0;
    const float inv1 = 1.0f / l1;
    float* out0 = Out + head_base + (size_t)(qt * BM + mrow + g) * DH;
    float* out1 = out0 + 8 * DH;
    #pragma unroll
    for (int n = 0; n < 8; ++n) {
        float2 v0 = make_float2(o[n][0] * inv0, o[n][1] * inv0);
        *reinterpret_cast<float2*>(out0 + n * 8 + 2 * j) = v0;
        float2 v1 = make_float2(o[n][2] * inv1, o[n][3] * inv1);
        *reinterpret_cast<float2*>(out1 + n * 8 + 2 * j) = v1;
    }
}

extern "C" void kernel_launch(void* const* d_in, const int* in_sizes, int n_in,
                              void* d_out, int out_size) {
    const float* K = (const float*)d_in[0];
    const float* Q = (const float*)d_in[1];
    const float* V = (const float*)d_in[2];
    float* O = (float*)d_out;

    cudaFuncSetAttribute(mha_fa_tf32,
                         cudaFuncAttributeMaxDynamicSharedMemorySize,
                         SMEM_BYTES);

    dim3 grid(S_LEN / BM, 2 * HEADS);  // 16 query tiles x 32 (b,h) heads
    mha_fa_tf32<<<grid, NTHREADS, SMEM_BYTES>>>(K, Q, V, O);
}

// round 6
// speedup vs baseline: 1.2992x; 1.2992x over previous
#include <cuda_runtime.h>
#include <cstdint>
#include <math_constants.h>

// Flash-attention, TF32 mma.sync, fp32 accumulate. Register-blocked:
// each warp owns 32 query rows (two m16 fragments) so K/V B-fragments are
// reused 2x -> smem crossbar bytes per row drop ~0.63x (crossbar was the
// measured binder: L1=58.6%, tensor=32.1%).
// B=2, H=16, S=2048, DK=DV=64. Output = raw reshape -> layout [B,H,S,DV].
// d_in[0]=key, d_in[1]=query, d_in[2]=value (fp32).

namespace {

constexpr int S_LEN    = 2048;
constexpr int DH       = 64;
constexpr int BM       = 256;   // query rows per CTA (32 per warp)
constexpr int BN       = 64;    // key rows per tile
constexpr int NTHREADS = 256;   // 8 warps
constexpr int NTILES   = S_LEN / BN;

// smem strides (words), conflict-free for the operand access patterns:
//  Q/K/P stride 68: bank = 4g + j   -> 32 distinct
//  V stride 72:     bank = 8j + g   -> 32 distinct
constexpr int QSTR = 68;
constexpr int KSTR = 68;
constexpr int VSTR = 72;
constexpr int PSTR = 68;

constexpr int SMEM_WORDS = BM * QSTR + BN * KSTR + BN * VSTR + BM * PSTR;
constexpr int SMEM_BYTES = SMEM_WORDS * 4;   // 175,104 B -> 1 CTA/SM

__device__ __forceinline__ uint32_t f2tf(float x) {
    uint32_t r;
    asm("cvt.rna.tf32.f32 %0, %1;" : "=r"(r) : "f"(x));
    return r;
}

__device__ __forceinline__ float fast_exp2(float x) {
    float y;
    asm("ex2.approx.ftz.f32 %0, %1;" : "=f"(y) : "f"(x));
    return y;
}

__device__ __forceinline__ void mma_tf32(float c[4],
                                         uint32_t a0, uint32_t a1,
                                         uint32_t a2, uint32_t a3,
                                         uint32_t b0, uint32_t b1) {
    asm volatile(
        "mma.sync.aligned.m16n8k8.row.col.f32.tf32.tf32.f32 "
        "{%0,%1,%2,%3}, {%4,%5,%6,%7}, {%8,%9}, {%0,%1,%2,%3};"
        : "+f"(c[0]), "+f"(c[1]), "+f"(c[2]), "+f"(c[3])
        : "r"(a0), "r"(a1), "r"(a2), "r"(a3), "r"(b0), "r"(b1));
}

}  // namespace

__global__ __launch_bounds__(NTHREADS, 1)
void mha_fa_tf32(const float* __restrict__ Kg,
                 const float* __restrict__ Qg,
                 const float* __restrict__ Vg,
                 float* __restrict__ Out) {
    extern __shared__ uint32_t smem[];
    uint32_t* sQ = smem;
    uint32_t* sK = sQ + BM * QSTR;
    uint32_t* sV = sK + BN * KSTR;
    uint32_t* sP = sV + BN * VSTR;

    const int tid   = threadIdx.x;
    const int warp  = tid >> 5;
    const int lane  = tid & 31;
    const int g     = lane >> 2;   // group id 0..7
    const int j     = lane & 3;    // quad id  0..3
    const int mbase = warp * 32;   // this warp's 32 query rows

    const int bh = blockIdx.y;     // b*16 + h
    const int qt = blockIdx.x;     // query tile

    const size_t head_base = (size_t)bh * S_LEN * DH;
    const float* Qp = Qg + head_base + (size_t)qt * BM * DH;
    const float* Kp = Kg + head_base;
    const float* Vp = Vg + head_base;

    // ---- load Q tile (pre-scaled by 1/sqrt(dk)=0.125), convert to tf32 ----
    for (int i = tid * 4; i < BM * DH; i += NTHREADS * 4) {
        float4 v = *reinterpret_cast<const float4*>(Qp + i);
        uint4 w;
        w.x = f2tf(v.x * 0.125f);
        w.y = f2tf(v.y * 0.125f);
        w.z = f2tf(v.z * 0.125f);
        w.w = f2tf(v.w * 0.125f);
        *reinterpret_cast<uint4*>(sQ + (i >> 6) * QSTR + (i & 63)) = w;
    }

    float o[2][8][4];
    #pragma unroll
    for (int m2 = 0; m2 < 2; ++m2)
        #pragma unroll
        for (int n = 0; n < 8; ++n)
            #pragma unroll
            for (int t = 0; t < 4; ++t) o[m2][n][t] = 0.f;

    float mrow[2][2] = {{-CUDART_INF_F, -CUDART_INF_F},
                        {-CUDART_INF_F, -CUDART_INF_F}};
    float lrow[2][2] = {{0.f, 0.f}, {0.f, 0.f}};
    const float L2E = 1.4426950408889634f;

    // ---- prefetch tile 0 into registers ----
    float4 pk[4], pv[4];
    #pragma unroll
    for (int i = 0; i < 4; ++i) {
        pk[i] = *reinterpret_cast<const float4*>(Kp + tid * 4 + i * 1024);
        pv[i] = *reinterpret_cast<const float4*>(Vp + tid * 4 + i * 1024);
    }

    for (int kt = 0; kt < NTILES; ++kt) {
        __syncthreads();  // previous tile's smem fully consumed (Q ready, iter 0)

        // ---- publish prefetched K/V tile (cvt to tf32) ----
        #pragma unroll
        for (int i = 0; i < 4; ++i) {
            const int idx = tid * 4 + i * 1024;
            const int r = idx >> 6, c = idx & 63;
            uint4 wk, wv;
            wk.x = f2tf(pk[i].x); wk.y = f2tf(pk[i].y);
            wk.z = f2tf(pk[i].z); wk.w = f2tf(pk[i].w);
            *reinterpret_cast<uint4*>(sK + r * KSTR + c) = wk;
            wv.x = f2tf(pv[i].x); wv.y = f2tf(pv[i].y);
            wv.z = f2tf(pv[i].z); wv.w = f2tf(pv[i].w);
            *reinterpret_cast<uint4*>(sV + r * VSTR + c) = wv;
        }
        __syncthreads();

        // ---- prefetch next tile (latency hides under compute) ----
        if (kt + 1 < NTILES) {
            const float* Kt = Kp + (kt + 1) * BN * DH;
            const float* Vt = Vp + (kt + 1) * BN * DH;
            #pragma unroll
            for (int i = 0; i < 4; ++i) {
                pk[i] = *reinterpret_cast<const float4*>(Kt + tid * 4 + i * 1024);
                pv[i] = *reinterpret_cast<const float4*>(Vt + tid * 4 + i * 1024);
            }
        }

        // ---- S = (Q*scale) @ K^T : 32x64 per warp, B frags reused 2x ----
        float c2[2][8][4];
        #pragma unroll
        for (int m2 = 0; m2 < 2; ++m2)
            #pragma unroll
            for (int n = 0; n < 8; ++n)
                #pragma unroll
                for (int t = 0; t < 4; ++t) c2[m2][n][t] = 0.f;

        #pragma unroll
        for (int k0 = 0; k0 < DH; k0 += 8) {
            uint32_t a[2][4];
            #pragma unroll
            for (int m2 = 0; m2 < 2; ++m2) {
                const int r0 = mbase + m2 * 16 + g;
                a[m2][0] = sQ[(r0    ) * QSTR + k0 + j];
                a[m2][1] = sQ[(r0 + 8) * QSTR + k0 + j];
                a[m2][2] = sQ[(r0    ) * QSTR + k0 + j + 4];
                a[m2][3] = sQ[(r0 + 8) * QSTR + k0 + j + 4];
            }
            #pragma unroll
            for (int n = 0; n < 8; ++n) {
                const uint32_t b0 = sK[(n * 8 + g) * KSTR + k0 + j];
                const uint32_t b1 = sK[(n * 8 + g) * KSTR + k0 + j + 4];
                #pragma unroll
                for (int m2 = 0; m2 < 2; ++m2)
                    mma_tf32(c2[m2][n], a[m2][0], a[m2][1], a[m2][2], a[m2][3],
                             b0, b1);
            }
        }

        // ---- online softmax, per m-fragment ----
        #pragma unroll
        for (int m2 = 0; m2 < 2; ++m2) {
            float mx0 = mrow[m2][0], mx1 = mrow[m2][1];
            #pragma unroll
            for (int n = 0; n < 8; ++n) {
                mx0 = fmaxf(mx0, fmaxf(c2[m2][n][0], c2[m2][n][1]));
                mx1 = fmaxf(mx1, fmaxf(c2[m2][n][2], c2[m2][n][3]));
            }
            mx0 = fmaxf(mx0, __shfl_xor_sync(0xffffffffu, mx0, 1));
            mx0 = fmaxf(mx0, __shfl_xor_sync(0xffffffffu, mx0, 2));
            mx1 = fmaxf(mx1, __shfl_xor_sync(0xffffffffu, mx1, 1));
            mx1 = fmaxf(mx1, __shfl_xor_sync(0xffffffffu, mx1, 2));

            const float sc0 = fast_exp2((mrow[m2][0] - mx0) * L2E);
            const float sc1 = fast_exp2((mrow[m2][1] - mx1) * L2E);
            mrow[m2][0] = mx0; mrow[m2][1] = mx1;

            const int r0 = mbase + m2 * 16 + g;
            float s0 = 0.f, s1 = 0.f;
            #pragma unroll
            for (int n = 0; n < 8; ++n) {
                const float p0 = fast_exp2((c2[m2][n][0] - mx0) * L2E);
                const float p1 = fast_exp2((c2[m2][n][1] - mx0) * L2E);
                const float p2 = fast_exp2((c2[m2][n][2] - mx1) * L2E);
                const float p3 = fast_exp2((c2[m2][n][3] - mx1) * L2E);
                s0 += p0 + p1;
                s1 += p2 + p3;
                sP[(r0    ) * PSTR + n * 8 + 2 * j    ] = f2tf(p0);
                sP[(r0    ) * PSTR + n * 8 + 2 * j + 1] = f2tf(p1);
                sP[(r0 + 8) * PSTR + n * 8 + 2 * j    ] = f2tf(p2);
                sP[(r0 + 8) * PSTR + n * 8 + 2 * j + 1] = f2tf(p3);
            }
            s0 += __shfl_xor_sync(0xffffffffu, s0, 1);
            s0 += __shfl_xor_sync(0xffffffffu, s0, 2);
            s1 += __shfl_xor_sync(0xffffffffu, s1, 1);
            s1 += __shfl_xor_sync(0xffffffffu, s1, 2);
            lrow[m2][0] = lrow[m2][0] * sc0 + s0;
            lrow[m2][1] = lrow[m2][1] * sc1 + s1;

            #pragma unroll
            for (int n = 0; n < 8; ++n) {
                o[m2][n][0] *= sc0; o[m2][n][1] *= sc0;
                o[m2][n][2] *= sc1; o[m2][n][3] *= sc1;
            }
        }

        __syncwarp();  // sP rows are warp-private

        // ---- O += P @ V : 32x64 per warp, V frags reused 2x ----
        #pragma unroll
        for (int k0 = 0; k0 < BN; k0 += 8) {
            uint32_t a[2][4];
            #pragma unroll
            for (int m2 = 0; m2 < 2; ++m2) {
                const int r0 = mbase + m2 * 16 + g;
                a[m2][0] = sP[(r0    ) * PSTR + k0 + j];
                a[m2][1] = sP[(r0 + 8) * PSTR + k0 + j];
                a[m2][2] = sP[(r0    ) * PSTR + k0 + j + 4];
                a[m2][3] = sP[(r0 + 8) * PSTR + k0 + j + 4];
            }
            #pragma unroll
            for (int n = 0; n < 8; ++n) {
                const uint32_t b0 = sV[(k0 + j    ) * VSTR + n * 8 + g];
                const uint32_t b1 = sV[(k0 + j + 4) * VSTR + n * 8 + g];
                #pragma unroll
                for (int m2 = 0; m2 < 2; ++m2)
                    mma_tf32(o[m2][n], a[m2][0], a[m2][1], a[m2][2], a[m2][3],
                             b0, b1);
            }
        }
    }

    // ---- epilogue: normalize + store (output layout = contiguous [B,H,S,DV]) ----
    #pragma unroll
    for (int m2 = 0; m2 < 2; ++m2) {
        const float inv0 = 1.0f / lrow[m2][0];
        const float inv1 = 1.0f / lrow[m2][1];
        float* out0 = Out + head_base
                    + (size_t)(qt * BM + mbase + m2 * 16 + g) * DH;
        float* out1 = out0 + 8 * DH;
        #pragma unroll
        for (int n = 0; n < 8; ++n) {
            float2 v0 = make_float2(o[m2][n][0] * inv0, o[m2][n][1] * inv0);
            *reinterpret_cast<float2*>(out0 + n * 8 + 2 * j) = v0;
            float2 v1 = make_float2(o[m2][n][2] * inv1, o[m2][n][3] * inv1);
            *reinterpret_cast<float2*>(out1 + n * 8 + 2 * j) = v1;
        }
    }
}

extern "C" void kernel_launch(void* const* d_in, const int* in_sizes, int n_in,
                              void* d_out, int out_size) {
    const float* K = (const float*)d_in[0];
    const float* Q = (const float*)d_in[1];
    const float* V = (const float*)d_in[2];
    float* O = (float*)d_out;

    cudaFuncSetAttribute(mha_fa_tf32,
                         cudaFuncAttributeMaxDynamicSharedMemorySize,
                         SMEM_BYTES);

    dim3 grid(S_LEN / BM, 32);  // 8 query tiles x 32 (b,h) heads = 256 CTAs
    mha_fa_tf32<<<grid, NTHREADS, SMEM_BYTES>>>(K, Q, V, O);
}